// round 3
// baseline (speedup 1.0000x reference)
#include <cuda_runtime.h>
#include <cstdint>
#include <cstddef>

#define BSZ   64
#define NI    2048
#define DI    8
#define NO    32
#define DOUT  16

#define BT    32
#define NCH   2
#define NTHREADS 512
#define GRID  148
#define ITEMS_PER_BT (NI / NCH)              // 1024
#define N_ITEMS (ITEMS_PER_BT * (BSZ / BT))  // 2048

typedef unsigned long long ull;

__device__ float g_s[BSZ * NO * DOUT];           // zero at entry (squash re-zeros)
__device__ float g_v[BSZ * NO * DOUT];
__device__ float g_blog[(size_t)BSZ * NI * NO];  // 16 MB logits
__device__ float g_pad;

static __device__ __forceinline__ ull pack2(float lo, float hi) {
    ull r; asm("mov.b64 %0,{%1,%2};" : "=l"(r) : "f"(lo), "f"(hi)); return r;
}
static __device__ __forceinline__ float2 unpk(ull v) {
    float2 r; asm("mov.b64 {%0,%1},%2;" : "=f"(r.x), "=f"(r.y) : "l"(v)); return r;
}
static __device__ __forceinline__ ull fma2(ull a, ull b, ull c) {
    ull d; asm("fma.rn.f32x2 %0,%1,%2,%3;" : "=l"(d) : "l"(a), "l"(b), "l"(c)); return d;
}
static __device__ __forceinline__ ull mul2(ull a, ull b) {
    ull d; asm("mul.rn.f32x2 %0,%1,%2;" : "=l"(d) : "l"(a), "l"(b)); return d;
}

// Pad kernel: shifts ncu -s 5 onto caps_pass<2> for next-round profiling.
__global__ void prof_pad_k() {}

// W SMEM layout per n (16 KB): pair-interleaved for fma2 operands.
//   float at off(o,dp,i,par) = o*512 + dp*64 + i*8 + par*4   (par: d=2dp+par)
//   swizzle: 16B-unit index XOR full 5-bit o  ->  off ^ (o<<4), conflict-free
//   for lanes (o in 8-block, dg 0..3) and for staging.
template <int PASS>
__global__ void __launch_bounds__(NTHREADS, 1)
caps_pass(const float* __restrict__ X, const float* __restrict__ W)
{
    extern __shared__ char sm[];
    char*   w_s = sm;                                 // NCH * 16384 = 32768 B
    float2* x_d = (float2*)(sm + 32768);              // 4096 B (x duplicated pairs)
    float*  v_s = (float*)(sm + 32768 + 4096);        // 65536 B
    float*  red = (float*)(sm + 32768 + 4096 + 65536);// 512 B

    const int tid = threadIdx.x;
    const int wg  = tid >> 7;         // warpgroup -> 8 batches
    const int wt  = tid & 127;
    const int o   = wt >> 2;          // output capsule
    const int dg  = wt & 3;           // d-quad
    const int wiw = (wt >> 5) & 3;
    const unsigned xo = (unsigned)o << 4;

    // staging coords: one 8-float unit per thread per n
    const int so  = tid >> 4;
    const int sdp = (tid >> 1) & 7;
    const int siq = tid & 1;
    const unsigned sxo = (unsigned)so << 4;

    const ull Z = pack2(0.f, 0.f);
    ull s0[8], s1[8];
#pragma unroll
    for (int b = 0; b < 8; b++) { s0[b] = Z; s1[b] = Z; }

    int cur_bt = -1;

    for (int it = blockIdx.x; it < N_ITEMS; it += GRID) {
        const int btile = it >> 10;                  // ITEMS_PER_BT = 1024
        const int n0    = (it & (ITEMS_PER_BT - 1)) * NCH;
        const bool newb = (btile != cur_bt);

        if (newb && cur_bt >= 0) {
#pragma unroll
            for (int bi = 0; bi < 8; bi++) {
                float* p = g_s + (size_t)(cur_bt * BT + wg * 8 + bi) * 512 + o * 16 + dg * 4;
                float2 a = unpk(s0[bi]); float2 b = unpk(s1[bi]);
                atomicAdd(p + 0, a.x); atomicAdd(p + 1, a.y);
                atomicAdd(p + 2, b.x); atomicAdd(p + 3, b.y);
                s0[bi] = Z; s1[bi] = Z;
            }
        }
        __syncthreads();   // prior item done reading w_s / x_d / v_s

        // ---- stage W (pair-interleaved, swizzled) ----
#pragma unroll
        for (int nn = 0; nn < NCH; nn++) {
            const float* gw = W + (size_t)(n0 + nn) * 4096 + so * 128 + sdp * 16 + siq * 4;
            float4 a = *(const float4*)gw;         // d = 2*sdp
            float4 c = *(const float4*)(gw + 8);   // d = 2*sdp + 1
            char* dst = w_s + nn * 16384 + so * 512;
            unsigned u = (unsigned)(sdp * 64 + siq * 32);
            *(float4*)(dst + (u ^ sxo))        = make_float4(a.x, c.x, a.y, c.y);
            *(float4*)(dst + ((u + 16) ^ sxo)) = make_float4(a.z, c.z, a.w, c.w);
        }
        // ---- stage x duplicated pairs ----
        {
            int b = tid >> 4, rem = tid & 15;      // 16 floats per batch (NCH*DI)
            float xv = X[(size_t)(btile * BT + b) * (NI * DI) + n0 * DI + rem];
            x_d[b * 16 + rem] = make_float2(xv, xv);
        }
        // ---- stage v on b-tile change ----
        if (PASS > 0 && newb) {
#pragma unroll
            for (int k = 0; k < 8; k++) {
                int f = k * 2048 + tid * 4;
                *(float4*)(v_s + f) = *(const float4*)(g_v + (size_t)btile * BT * 512 + f);
            }
        }
        cur_bt = btile;
        __syncthreads();

#pragma unroll
        for (int nn = 0; nn < NCH; nn++) {
            const int n = n0 + nn;

            // W regs: 8 conflict-free LDS.128 -> 16 ull fma2 operands (no packing movs)
            ull w0[8], w1[8];
            const char* wb = w_s + nn * 16384 + o * 512;
#pragma unroll
            for (int ip = 0; ip < 4; ip++) {
                ulonglong2 uA = *(const ulonglong2*)(wb + ((unsigned)((dg * 2 + 0) * 64 + ip * 16) ^ xo));
                ulonglong2 uB = *(const ulonglong2*)(wb + ((unsigned)((dg * 2 + 1) * 64 + ip * 16) ^ xo));
                w0[2 * ip] = uA.x; w0[2 * ip + 1] = uA.y;
                w1[2 * ip] = uB.x; w1[2 * ip + 1] = uB.y;
            }

            if (PASS == 0) {
                const ull C = pack2(0.03125f, 0.03125f);
#pragma unroll
                for (int bi = 0; bi < 8; bi++) {
                    const ulonglong2* xq = (const ulonglong2*)(x_d + (wg * 8 + bi) * 16 + nn * 8);
                    ulonglong2 qa = xq[0], qb = xq[1], qc = xq[2], qd = xq[3];
                    ull h0 = Z, h1 = Z;
                    h0 = fma2(w0[0], qa.x, h0); h1 = fma2(w1[0], qa.x, h1);
                    h0 = fma2(w0[1], qa.y, h0); h1 = fma2(w1[1], qa.y, h1);
                    h0 = fma2(w0[2], qb.x, h0); h1 = fma2(w1[2], qb.x, h1);
                    h0 = fma2(w0[3], qb.y, h0); h1 = fma2(w1[3], qb.y, h1);
                    h0 = fma2(w0[4], qc.x, h0); h1 = fma2(w1[4], qc.x, h1);
                    h0 = fma2(w0[5], qc.y, h0); h1 = fma2(w1[5], qc.y, h1);
                    h0 = fma2(w0[6], qd.x, h0); h1 = fma2(w1[6], qd.x, h1);
                    h0 = fma2(w0[7], qd.y, h0); h1 = fma2(w1[7], qd.y, h1);
                    s0[bi] = fma2(C, h0, s0[bi]);
                    s1[bi] = fma2(C, h1, s1[bi]);
                }
            } else {
#pragma unroll
                for (int g = 0; g < 2; g++) {
                    ull t0[4], t1[4];
#pragma unroll
                    for (int q = 0; q < 4; q++) {
                        const int bi = g * 4 + q, bloc = wg * 8 + bi;
                        float bp = 0.f;
                        if (PASS == 2 && dg == 0)
                            bp = g_blog[(size_t)(cur_bt * BT + bloc) * (NI * NO) + (size_t)n * NO + o];

                        const ulonglong2* xq = (const ulonglong2*)(x_d + bloc * 16 + nn * 8);
                        ulonglong2 qa = xq[0], qb = xq[1], qc = xq[2], qd = xq[3];
                        ull h0 = Z, h1 = Z;
                        h0 = fma2(w0[0], qa.x, h0); h1 = fma2(w1[0], qa.x, h1);
                        h0 = fma2(w0[1], qa.y, h0); h1 = fma2(w1[1], qa.y, h1);
                        h0 = fma2(w0[2], qb.x, h0); h1 = fma2(w1[2], qb.x, h1);
                        h0 = fma2(w0[3], qb.y, h0); h1 = fma2(w1[3], qb.y, h1);
                        h0 = fma2(w0[4], qc.x, h0); h1 = fma2(w1[4], qc.x, h1);
                        h0 = fma2(w0[5], qc.y, h0); h1 = fma2(w1[5], qc.y, h1);
                        h0 = fma2(w0[6], qd.x, h0); h1 = fma2(w1[6], qd.x, h1);
                        h0 = fma2(w0[7], qd.y, h0); h1 = fma2(w1[7], qd.y, h1);

                        // dot over this thread's 4 d's (vv conflict-free: unit o*4+dg)
                        const ulonglong2 vv = *(const ulonglong2*)(v_s + (bloc * NO + o) * DOUT + dg * 4);
                        float2 tf = unpk(fma2(h1, vv.y, mul2(h0, vv.x)));
                        float t = tf.x + tf.y + bp;
                        t += __shfl_xor_sync(0xffffffffu, t, 1);
                        t += __shfl_xor_sync(0xffffffffu, t, 2);   // full 16-d dot (+blog)
                        if (PASS == 1 && dg == 0)
                            g_blog[(size_t)(cur_bt * BT + bloc) * (NI * NO) + (size_t)n * NO + o] = t;

                        float e = __expf(t);        // |t| small: safe
                        ull ee = pack2(e, e);
                        t0[q] = mul2(ee, h0);       // e*xhat: lives across barrier
                        t1[q] = mul2(ee, h1);
                        float ws = e;
                        ws += __shfl_xor_sync(0xffffffffu, ws, 4);
                        ws += __shfl_xor_sync(0xffffffffu, ws, 8);
                        ws += __shfl_xor_sync(0xffffffffu, ws, 16);
                        if ((tid & 31) == 0) red[g * 64 + wg * 16 + q * 4 + wiw] = ws;
                    }
                    asm volatile("bar.sync %0, 128;" :: "r"(wg + 1) : "memory");
#pragma unroll
                    for (int q = 0; q < 4; q++) {
                        const int bi = g * 4 + q;
                        float4 r4 = *(const float4*)(red + g * 64 + wg * 16 + q * 4);
                        float rc = __fdividef(1.f, (r4.x + r4.y) + (r4.z + r4.w));
                        ull cc = pack2(rc, rc);
                        s0[bi] = fma2(cc, t0[q], s0[bi]);
                        s1[bi] = fma2(cc, t1[q], s1[bi]);
                    }
                }
            }
        }
    }

    // final flush
#pragma unroll
    for (int bi = 0; bi < 8; bi++) {
        float* p = g_s + (size_t)(cur_bt * BT + wg * 8 + bi) * 512 + o * 16 + dg * 4;
        float2 a = unpk(s0[bi]); float2 b = unpk(s1[bi]);
        atomicAdd(p + 0, a.x); atomicAdd(p + 1, a.y);
        atomicAdd(p + 2, b.x); atomicAdd(p + 3, b.y);
    }
}

// v = squash(s); re-zeros g_s so every pass / graph replay starts clean.
__global__ void squash_k(float* __restrict__ extout)
{
    int t = blockIdx.x * 256 + threadIdx.x;   // 8192 threads
    float4 s4 = *(const float4*)(g_s + t * 4);
    float sq = s4.x * s4.x + s4.y * s4.y + s4.z * s4.z + s4.w * s4.w;
    sq += __shfl_xor_sync(0xffffffffu, sq, 1);
    sq += __shfl_xor_sync(0xffffffffu, sq, 2);
    float f = sqrtf(sq) / (1.0f + sq);
    float4 v4 = make_float4(s4.x * f, s4.y * f, s4.z * f, s4.w * f);
    float* dst = extout ? extout : g_v;
    *(float4*)(dst + t * 4) = v4;
    *(float4*)(g_s + t * 4) = make_float4(0.f, 0.f, 0.f, 0.f);
}

extern "C" void kernel_launch(void* const* d_in, const int* in_sizes, int n_in,
                              void* d_out, int out_size)
{
    const float* X = (const float*)d_in[0];
    const float* W = (const float*)d_in[1];
    if (in_sizes[0] != BSZ * NI * DI) { X = (const float*)d_in[1]; W = (const float*)d_in[0]; }

    const int smem = 32768 + 4096 + 65536 + 512;   // 102912 B
    cudaFuncSetAttribute(caps_pass<0>, cudaFuncAttributeMaxDynamicSharedMemorySize, smem);
    cudaFuncSetAttribute(caps_pass<1>, cudaFuncAttributeMaxDynamicSharedMemorySize, smem);
    cudaFuncSetAttribute(caps_pass<2>, cudaFuncAttributeMaxDynamicSharedMemorySize, smem);

    prof_pad_k<<<1, 32>>>();   // shifts ncu -s 5 onto caps_pass<2>
    caps_pass<0><<<GRID, NTHREADS, smem>>>(X, W);
    squash_k<<<32, 256>>>((float*)nullptr);
    caps_pass<1><<<GRID, NTHREADS, smem>>>(X, W);
    squash_k<<<32, 256>>>((float*)nullptr);
    caps_pass<2><<<GRID, NTHREADS, smem>>>(X, W);
    squash_k<<<32, 256>>>((float*)d_out);
}